// round 10
// baseline (speedup 1.0000x reference)
#include <cuda_runtime.h>
#include <cuda_fp16.h>
#include <cstdint>

#define Bsz 1024
#define Gdim 2048
#define Edim 256
#define Hdim 32
#define Vdim 14463
#define Vpad 14592   // 114 * 128
#define Tdim 18
#define Sdim 18      // last step's output is dropped
#define G4  128      // 4*H
#define Mtot (Bsz * Sdim)   // 18432
#define WCVT_BLOCKS 1824    // Vpad*32/256
#define INIT_BLOCKS 1024    // Bsz*Edim/256

// ---- scratch (no cudaMalloc allowed) ----
__device__ float g_init[Bsz * Edim];                       // graph projection
__device__ float g_gx0[Bsz * Sdim * G4];                   // L0 input-gates precompute
__device__ __align__(16) __half g_h2cv[Mtot * 32];         // h2 rows: fp16, 32/row
__device__ __align__(16) __half g_wcv[(size_t)Vpad * 32];  // Wout rows: fp16, 32/row

// ================= packed f32x2 helpers =================
static __device__ __forceinline__ unsigned long long pk2(float lo, float hi) {
    unsigned long long r;
    asm("mov.b64 %0, {%1,%2};" : "=l"(r) : "f"(lo), "f"(hi));
    return r;
}
static __device__ __forceinline__ unsigned long long fma2(unsigned long long a,
                                                          unsigned long long b,
                                                          unsigned long long c) {
    unsigned long long d;
    asm("fma.rn.f32x2 %0, %1, %2, %3;" : "=l"(d) : "l"(a), "l"(b), "l"(c));
    return d;
}
static __device__ __forceinline__ float2 up2(unsigned long long v) {
    float2 f;
    asm("mov.b64 {%0,%1}, %2;" : "=f"(f.x), "=f"(f.y) : "l"(v));
    return f;
}
static __device__ __forceinline__ float sigf(float x) {
    return 1.0f / (1.0f + __expf(-x));
}

static __device__ __forceinline__ uint32_t smem_u32(const void* p) {
    uint32_t a;
    asm("{ .reg .u64 t; cvta.to.shared.u64 t, %1; cvt.u32.u64 %0, t; }" : "=r"(a) : "l"(p));
    return a;
}
#define SW64(o)  ((o) ^ (((o) >> 3) & 0x30))

#define LDSM_X4(r0, r1, r2, r3, addr) \
    asm volatile("ldmatrix.sync.aligned.m8n8.x4.shared.b16 {%0,%1,%2,%3}, [%4];" \
        : "=r"(r0), "=r"(r1), "=r"(r2), "=r"(r3) : "r"(addr))

#define MMA16816F16(c, a, b) \
    asm volatile("mma.sync.aligned.m16n8k16.row.col.f32.f16.f16.f32 " \
        "{%0,%1,%2,%3}, {%4,%5,%6,%7}, {%8,%9}, {%0,%1,%2,%3};" \
        : "+f"((c)[0]), "+f"((c)[1]), "+f"((c)[2]), "+f"((c)[3]) \
        : "r"((a)[0]), "r"((a)[1]), "r"((a)[2]), "r"((a)[3]), \
          "r"((b)[0]), "r"((b)[1]))

// ============================================================
// K0: fused streaming init —
//     blocks [0, WCVT_BLOCKS)            : W_out -> fp16 convert+pad
//     blocks [WCVT_BLOCKS, +INIT_BLOCKS) : g_init = broadcast bias
// ============================================================
__global__ void k_init(const float* __restrict__ Wout,
                       const float* __restrict__ b_g2e) {
    if (blockIdx.x < WCVT_BLOCKS) {
        int i = blockIdx.x * 256 + threadIdx.x;
        int v = i >> 5, k = i & 31;
        float val = (v < Vdim) ? Wout[v * 32 + k] : 0.f;
        g_wcv[(size_t)v * 32 + k] = __float2half_rn(val);
    } else {
        int i = (blockIdx.x - WCVT_BLOCKS) * 256 + threadIdx.x;
        g_init[i] = b_g2e[i & (Edim - 1)];
    }
}

// ============================================================
// K1: g_init += graph_embedding @ W_g2e^T  (split-K=8, f32x2)  [R6/R9 form]
// ============================================================
__global__ __launch_bounds__(256) void k_proj(const float* __restrict__ A,
                                              const float* __restrict__ W) {
    __shared__ __align__(16) float As[32][64];
    __shared__ __align__(16) float Bs[32][64];
    const int tid = threadIdx.x;
    const int m0 = blockIdx.y * 64;
    const int n0 = blockIdx.x * 64;
    const int kbase = blockIdx.z * 256;

    const int tx = tid & 15, ty = tid >> 4;
    const int r = tid & 63, h = tid >> 6;

    const float* Ap = A + (size_t)(m0 + r) * Gdim + kbase;
    const float* Wp = W + (size_t)(n0 + r) * Gdim + kbase;

    unsigned long long acc[4][2];
#pragma unroll
    for (int j = 0; j < 4; j++) { acc[j][0] = 0ull; acc[j][1] = 0ull; }

    for (int kc = 0; kc < 256; kc += 32) {
#pragma unroll
        for (int i = 0; i < 2; i++) {
            int seg = h + i * 4;
            float4 va = *(const float4*)(Ap + kc + seg * 4);
            As[seg * 4 + 0][r] = va.x; As[seg * 4 + 1][r] = va.y;
            As[seg * 4 + 2][r] = va.z; As[seg * 4 + 3][r] = va.w;
            float4 vb = *(const float4*)(Wp + kc + seg * 4);
            Bs[seg * 4 + 0][r] = vb.x; Bs[seg * 4 + 1][r] = vb.y;
            Bs[seg * 4 + 2][r] = vb.z; Bs[seg * 4 + 3][r] = vb.w;
        }
        __syncthreads();
#pragma unroll 8
        for (int k = 0; k < 32; k++) {
            ulonglong2 a = *(const ulonglong2*)&As[k][ty * 4];
#pragma unroll
            for (int j = 0; j < 4; j++) {
                float bv = Bs[k][tx + j * 16];
                unsigned long long bd = pk2(bv, bv);
                acc[j][0] = fma2(a.x, bd, acc[j][0]);
                acc[j][1] = fma2(a.y, bd, acc[j][1]);
            }
        }
        __syncthreads();
    }
#pragma unroll
    for (int j = 0; j < 4; j++) {
        int n = n0 + tx + j * 16;
#pragma unroll
        for (int p = 0; p < 2; p++) {
            float2 v = up2(acc[j][p]);
            int m = m0 + ty * 4 + p * 2;
            atomicAdd(&g_init[m * Edim + n], v.x);
            atomicAdd(&g_init[(m + 1) * Edim + n], v.y);
        }
    }
}

// ============================================================
// K2: g_gx0 = x @ W_ih0^T + (b_ih0 + b_hh0), x gathered.
//     M-tile 32 -> 576 CTAs (4/SM) for latency hiding.
// ============================================================
__global__ __launch_bounds__(256) void k_gx(const int* __restrict__ sent,
                                            const float* __restrict__ emb,
                                            const float* __restrict__ Wih0,
                                            const float* __restrict__ bih0,
                                            const float* __restrict__ bhh0) {
    __shared__ __align__(16) float As[32][32];
    __shared__ __align__(16) float Bs[32][128];
    const int tid = threadIdx.x;
    const int m0 = blockIdx.x * 32;
    const int tx = tid & 15, ty = tid >> 4;        // out: cols tx+j*16, rows ty*2..+1

    const int r = tid & 31, h = tid >> 5;          // A loader: row r, k seg h
    const int m = m0 + r;
    const int b = m / Sdim, s = m - b * Sdim;
    const float* Ap = (s == 0) ? (g_init + (size_t)b * Edim)
                               : (emb + (size_t)sent[b * Tdim + (s - 1)] * Edim);
    const int rb = tid & 127, hb = tid >> 7;       // B loader
    const float* Bp = Wih0 + (size_t)rb * Edim;

    unsigned long long acc[8];
#pragma unroll
    for (int j = 0; j < 8; j++) acc[j] = 0ull;

    for (int kc = 0; kc < 256; kc += 32) {
        {
            float4 v = *(const float4*)(Ap + kc + h * 4);
            As[h * 4 + 0][r] = v.x; As[h * 4 + 1][r] = v.y;
            As[h * 4 + 2][r] = v.z; As[h * 4 + 3][r] = v.w;
        }
#pragma unroll
        for (int i = 0; i < 4; i++) {
            int seg = i * 2 + hb;
            float4 v = *(const float4*)(Bp + kc + seg * 4);
            Bs[seg * 4 + 0][rb] = v.x; Bs[seg * 4 + 1][rb] = v.y;
            Bs[seg * 4 + 2][rb] = v.z; Bs[seg * 4 + 3][rb] = v.w;
        }
        __syncthreads();
#pragma unroll 8
        for (int k = 0; k < 32; k++) {
            unsigned long long a = *(const unsigned long long*)&As[k][ty * 2];
#pragma unroll
            for (int j = 0; j < 8; j++) {
                float bv = Bs[k][tx + j * 16];
                acc[j] = fma2(a, pk2(bv, bv), acc[j]);
            }
        }
        __syncthreads();
    }
#pragma unroll
    for (int j = 0; j < 8; j++) {
        int n = tx + j * 16;
        float bias = bih0[n] + bhh0[n];
        float2 v = up2(acc[j]);
        int mm = m0 + ty * 2;
        g_gx0[mm * G4 + n] = v.x + bias;
        g_gx0[(mm + 1) * G4 + n] = v.y + bias;
    }
}

// ============================================================
// K3: fused 2-layer LSTM, 18 steps. 1 batch row per warp,
//     256 thr/block, 128 blocks. Emits h2 as fp16 rows (32/row).
// ============================================================
__global__ __launch_bounds__(256) void k_lstm(const float* __restrict__ Whh0,
                                              const float* __restrict__ Wih1,
                                              const float* __restrict__ Whh1,
                                              const float* __restrict__ bih1,
                                              const float* __restrict__ bhh1) {
    __shared__ __align__(16) float W0[32 * 128];   // [k][j][q]
    __shared__ __align__(16) float Wi1[32 * 128];
    __shared__ __align__(16) float Wh1[32 * 128];
    const int tid = threadIdx.x;

    for (int idx = tid; idx < 4096; idx += 256) {
        int k = idx >> 7, rem = idx & 127, j = rem >> 2, q = rem & 3;
        int src = (q * 32 + j) * 32 + k;
        W0[idx]  = Whh0[src];
        Wi1[idx] = Wih1[src];
        Wh1[idx] = Whh1[src];
    }
    __syncthreads();

    const int wid = tid >> 5, j = tid & 31;
    const int brow = blockIdx.x * 8 + wid;

    float b1q[4];
#pragma unroll
    for (int q = 0; q < 4; q++) b1q[q] = bih1[q * 32 + j] + bhh1[q * 32 + j];

    float hA = 0.f, cA = 0.f, hB = 0.f, cB = 0.f;

    float pre[4];
    {
        int m = brow * Sdim;
#pragma unroll
        for (int q = 0; q < 4; q++) pre[q] = g_gx0[m * G4 + q * 32 + j];
    }

    for (int s = 0; s < Sdim; s++) {
        float gl[4];
#pragma unroll
        for (int q = 0; q < 4; q++) gl[q] = pre[q];
        if (s < Sdim - 1) {
            int m = brow * Sdim + s + 1;
#pragma unroll
            for (int q = 0; q < 4; q++) pre[q] = g_gx0[m * G4 + q * 32 + j];
        }
        // layer 0
#pragma unroll
        for (int k = 0; k < 32; k++) {
            float4 w = *(const float4*)&W0[k * 128 + j * 4];
            float h0 = __shfl_sync(0xffffffffu, hA, k);
            gl[0] += w.x * h0; gl[1] += w.y * h0;
            gl[2] += w.z * h0; gl[3] += w.w * h0;
        }
        {
            float ci = sigf(gl[0]), cf = sigf(gl[1]);
            float cg = tanhf(gl[2]), co = sigf(gl[3]);
            cA = cf * cA + ci * cg;
            hA = co * tanhf(cA);
        }
        // layer 1
        float G[4];
#pragma unroll
        for (int q = 0; q < 4; q++) G[q] = b1q[q];
#pragma unroll
        for (int k = 0; k < 32; k++) {
            float4 wi = *(const float4*)&Wi1[k * 128 + j * 4];
            float4 wh = *(const float4*)&Wh1[k * 128 + j * 4];
            float a0 = __shfl_sync(0xffffffffu, hA, k);
            float p0 = __shfl_sync(0xffffffffu, hB, k);
            G[0] += wi.x * a0 + wh.x * p0; G[1] += wi.y * a0 + wh.y * p0;
            G[2] += wi.z * a0 + wh.z * p0; G[3] += wi.w * a0 + wh.w * p0;
        }
        {
            float ci = sigf(G[0]), cf = sigf(G[1]);
            float cg = tanhf(G[2]), co = sigf(G[3]);
            cB = cf * cB + ci * cg;
            hB = co * tanhf(cB);
            g_h2cv[(size_t)(brow * Sdim + s) * 32 + j] = __float2half_rn(hB);
        }
    }
}

// ============================================================
// K4: mma.sync fp16 GEMM  out[18432, 14463] = h2 @ Wout^T + bias
//     [R8 form, measured 223.6us] CTA tile 128x128, 8 warps, K=32.
//     Single-pass epilogue via smem (pitch 136, conflict-free).
// ============================================================
#define EPI_PITCH 136
#define K4_SMEM (128 * EPI_PITCH * 4)   // 69632; staging (16KB) overlays

__global__ __launch_bounds__(256, 2) void k_out_mma(const float* __restrict__ bout,
                                                    float* __restrict__ out) {
    extern __shared__ __align__(1024) char sm[];
    __half* As = (__half*)sm;                 // 8 KB: 128 rows x 64B, SW64
    __half* Bs = (__half*)(sm + 8192);        // 8 KB: 128 rows x 64B, SW64
    float*  epi = (float*)sm;                 // overlay, 128 x 136 floats

    const int tid = threadIdx.x;
    const int wid = tid >> 5, lane = tid & 31;
    const int n0 = blockIdx.x * 128;
    const int m0 = blockIdx.y * 128;

    // ---- stage A and B (512 int4 each; 2 per thread) ----
    const int4* Ag = (const int4*)(g_h2cv + (size_t)m0 * 32);
    const int4* Bg = (const int4*)(g_wcv + (size_t)n0 * 32);
#pragma unroll
    for (int it = 0; it < 2; it++) {
        int idx = tid + it * 256;
        int row = idx >> 2, u = idx & 3;
        uint32_t off = (uint32_t)(row * 64 + u * 16);
        *(int4*)((char*)As + SW64(off)) = Ag[idx];
        *(int4*)((char*)Bs + SW64(off)) = Bg[idx];
    }

    float bias_r[4];
#pragma unroll
    for (int c = 0; c < 4; c++) {
        int col = n0 + c * 32 + lane;
        bias_r[c] = (col < Vdim) ? bout[col] : 0.f;
    }
    __syncthreads();

    const uint32_t As_u = smem_u32(As);
    const uint32_t Bs_u = smem_u32(Bs);

    const int mwarp = (wid & 3) * 32;
    const int nwarp = (wid >> 2) * 64;
    const int rowa = lane & 15;
    const int sega = lane >> 4;

    float acc[2][8][4];
#pragma unroll
    for (int mf = 0; mf < 2; mf++)
#pragma unroll
        for (int j = 0; j < 8; j++)
#pragma unroll
            for (int q = 0; q < 4; q++) acc[mf][j][q] = 0.f;

#pragma unroll
    for (int p = 0; p < 2; p++) {                 // two k16 steps (K=32)
        uint32_t a[2][4];
#pragma unroll
        for (int mf = 0; mf < 2; mf++) {
            uint32_t off = (uint32_t)((mwarp + mf * 16 + rowa) * 64 + p * 32 + sega * 16);
            LDSM_X4(a[mf][0], a[mf][1], a[mf][2], a[mf][3], As_u + SW64(off));
        }
        uint32_t bfr[8][2];
#pragma unroll
        for (int nb = 0; nb < 4; nb++) {
            uint32_t r0, r1, r2, r3;
            uint32_t off = (uint32_t)((nwarp + nb * 16 + rowa) * 64 + p * 32 + sega * 16);
            LDSM_X4(r0, r1, r2, r3, Bs_u + SW64(off));
            bfr[nb * 2][0] = r0;     bfr[nb * 2][1] = r2;
            bfr[nb * 2 + 1][0] = r1; bfr[nb * 2 + 1][1] = r3;
        }
#pragma unroll
        for (int mf = 0; mf < 2; mf++)
#pragma unroll
            for (int j = 0; j < 8; j++)
                MMA16816F16(acc[mf][j], a[mf], bfr[j]);
    }

    // ---- single-pass epilogue: all accs -> smem, then coalesced stores ----
    __syncthreads();          // staging reads complete; overlay is safe
#pragma unroll
    for (int mf = 0; mf < 2; mf++)
#pragma unroll
        for (int j = 0; j < 8; j++) {
            int colb = nwarp + j * 8 + (lane & 3) * 2;
            int r0 = mwarp + mf * 16 + (lane >> 2);
            *(float2*)&epi[r0 * EPI_PITCH + colb] =
                make_float2(acc[mf][j][0], acc[mf][j][1]);
            *(float2*)&epi[(r0 + 8) * EPI_PITCH + colb] =
                make_float2(acc[mf][j][2], acc[mf][j][3]);
        }
    __syncthreads();

    const int rbase = wid * 16;
#pragma unroll
    for (int rr = 0; rr < 16; rr++) {
        size_t gro = (size_t)(m0 + rbase + rr) * Vdim + n0;
#pragma unroll
        for (int c = 0; c < 4; c++) {
            int col = c * 32 + lane;
            if (n0 + col < Vdim)
                out[gro + col] = epi[(rbase + rr) * EPI_PITCH + col] + bias_r[c];
        }
    }
}

// ============================================================
extern "C" void kernel_launch(void* const* d_in, const int* in_sizes, int n_in,
                              void* d_out, int out_size) {
    const float* graph = (const float*)d_in[0];
    const int*   sent  = (const int*)d_in[1];
    const float* Wg2e  = (const float*)d_in[2];
    const float* bg2e  = (const float*)d_in[3];
    const float* emb   = (const float*)d_in[4];
    const float* Wih0  = (const float*)d_in[5];
    const float* Whh0  = (const float*)d_in[6];
    const float* bih0  = (const float*)d_in[7];
    const float* bhh0  = (const float*)d_in[8];
    const float* Wih1  = (const float*)d_in[9];
    const float* Whh1  = (const float*)d_in[10];
    const float* bih1  = (const float*)d_in[11];
    const float* bhh1  = (const float*)d_in[12];
    const float* Wout  = (const float*)d_in[13];
    const float* bout  = (const float*)d_in[14];
    float* out = (float*)d_out;

    cudaFuncSetAttribute(k_out_mma, cudaFuncAttributeMaxDynamicSharedMemorySize,
                         K4_SMEM);

    k_init<<<WCVT_BLOCKS + INIT_BLOCKS, 256>>>(Wout, bg2e);
    k_proj<<<dim3(4, 16, 8), 256>>>(graph, Wg2e);
    k_gx<<<576, 256>>>(sent, emb, Wih0, bih0, bhh0);
    k_lstm<<<128, 256>>>(Whh0, Wih1, Whh1, bih1, bhh1);
    k_out_mma<<<dim3(113, 144), 256, K4_SMEM>>>(bout, out);
}

// round 11
// speedup vs baseline: 1.0599x; 1.0599x over previous
#include <cuda_runtime.h>
#include <cuda_fp16.h>
#include <cstdint>

#define Bsz 1024
#define Gdim 2048
#define Edim 256
#define Hdim 32
#define Vdim 14463
#define Vpad 14592   // 114 * 128
#define Tdim 18
#define Sdim 18      // last step's output is dropped
#define G4  128      // 4*H
#define Mtot (Bsz * Sdim)   // 18432
#define WCVT_BLOCKS 1824    // Vpad*32/256
#define INIT_BLOCKS 1024    // Bsz*Edim/256

// ---- scratch (no cudaMalloc allowed) ----
__device__ float g_init[Bsz * Edim];                       // graph projection
__device__ float g_gx0[Bsz * Sdim * G4];                   // L0 input-gates precompute
__device__ __align__(16) __half g_h2cv[Mtot * 32];         // h2 rows: fp16, 32/row
__device__ __align__(16) __half g_wcv[(size_t)Vpad * 32];  // Wout rows: fp16, 32/row

// ================= packed f32x2 helpers =================
static __device__ __forceinline__ unsigned long long pk2(float lo, float hi) {
    unsigned long long r;
    asm("mov.b64 %0, {%1,%2};" : "=l"(r) : "f"(lo), "f"(hi));
    return r;
}
static __device__ __forceinline__ unsigned long long fma2(unsigned long long a,
                                                          unsigned long long b,
                                                          unsigned long long c) {
    unsigned long long d;
    asm("fma.rn.f32x2 %0, %1, %2, %3;" : "=l"(d) : "l"(a), "l"(b), "l"(c));
    return d;
}
static __device__ __forceinline__ float2 up2(unsigned long long v) {
    float2 f;
    asm("mov.b64 {%0,%1}, %2;" : "=f"(f.x), "=f"(f.y) : "l"(v));
    return f;
}
static __device__ __forceinline__ float sigf(float x) {
    return 1.0f / (1.0f + __expf(-x));
}

static __device__ __forceinline__ uint32_t smem_u32(const void* p) {
    uint32_t a;
    asm("{ .reg .u64 t; cvta.to.shared.u64 t, %1; cvt.u32.u64 %0, t; }" : "=r"(a) : "l"(p));
    return a;
}
#define SW64(o)  ((o) ^ (((o) >> 3) & 0x30))

#define LDSM_X4(r0, r1, r2, r3, addr) \
    asm volatile("ldmatrix.sync.aligned.m8n8.x4.shared.b16 {%0,%1,%2,%3}, [%4];" \
        : "=r"(r0), "=r"(r1), "=r"(r2), "=r"(r3) : "r"(addr))

#define MMA16816F16(c, a, b) \
    asm volatile("mma.sync.aligned.m16n8k16.row.col.f32.f16.f16.f32 " \
        "{%0,%1,%2,%3}, {%4,%5,%6,%7}, {%8,%9}, {%0,%1,%2,%3};" \
        : "+f"((c)[0]), "+f"((c)[1]), "+f"((c)[2]), "+f"((c)[3]) \
        : "r"((a)[0]), "r"((a)[1]), "r"((a)[2]), "r"((a)[3]), \
          "r"((b)[0]), "r"((b)[1]))

// ============================================================
// K0: fused streaming init —
//     blocks [0, WCVT_BLOCKS)            : W_out -> fp16 convert+pad
//     blocks [WCVT_BLOCKS, +INIT_BLOCKS) : g_init = broadcast bias
// ============================================================
__global__ void k_init(const float* __restrict__ Wout,
                       const float* __restrict__ b_g2e) {
    if (blockIdx.x < WCVT_BLOCKS) {
        int i = blockIdx.x * 256 + threadIdx.x;
        int v = i >> 5, k = i & 31;
        float val = (v < Vdim) ? Wout[v * 32 + k] : 0.f;
        g_wcv[(size_t)v * 32 + k] = __float2half_rn(val);
    } else {
        int i = (blockIdx.x - WCVT_BLOCKS) * 256 + threadIdx.x;
        g_init[i] = b_g2e[i & (Edim - 1)];
    }
}

// ============================================================
// K1: g_init += graph_embedding @ W_g2e^T  (split-K=8, f32x2)  [R9 form]
// ============================================================
__global__ __launch_bounds__(256) void k_proj(const float* __restrict__ A,
                                              const float* __restrict__ W) {
    __shared__ __align__(16) float As[32][64];
    __shared__ __align__(16) float Bs[32][64];
    const int tid = threadIdx.x;
    const int m0 = blockIdx.y * 64;
    const int n0 = blockIdx.x * 64;
    const int kbase = blockIdx.z * 256;

    const int tx = tid & 15, ty = tid >> 4;
    const int r = tid & 63, h = tid >> 6;

    const float* Ap = A + (size_t)(m0 + r) * Gdim + kbase;
    const float* Wp = W + (size_t)(n0 + r) * Gdim + kbase;

    unsigned long long acc[4][2];
#pragma unroll
    for (int j = 0; j < 4; j++) { acc[j][0] = 0ull; acc[j][1] = 0ull; }

    for (int kc = 0; kc < 256; kc += 32) {
#pragma unroll
        for (int i = 0; i < 2; i++) {
            int seg = h + i * 4;
            float4 va = *(const float4*)(Ap + kc + seg * 4);
            As[seg * 4 + 0][r] = va.x; As[seg * 4 + 1][r] = va.y;
            As[seg * 4 + 2][r] = va.z; As[seg * 4 + 3][r] = va.w;
            float4 vb = *(const float4*)(Wp + kc + seg * 4);
            Bs[seg * 4 + 0][r] = vb.x; Bs[seg * 4 + 1][r] = vb.y;
            Bs[seg * 4 + 2][r] = vb.z; Bs[seg * 4 + 3][r] = vb.w;
        }
        __syncthreads();
#pragma unroll 8
        for (int k = 0; k < 32; k++) {
            ulonglong2 a = *(const ulonglong2*)&As[k][ty * 4];
#pragma unroll
            for (int j = 0; j < 4; j++) {
                float bv = Bs[k][tx + j * 16];
                unsigned long long bd = pk2(bv, bv);
                acc[j][0] = fma2(a.x, bd, acc[j][0]);
                acc[j][1] = fma2(a.y, bd, acc[j][1]);
            }
        }
        __syncthreads();
    }
#pragma unroll
    for (int j = 0; j < 4; j++) {
        int n = n0 + tx + j * 16;
#pragma unroll
        for (int p = 0; p < 2; p++) {
            float2 v = up2(acc[j][p]);
            int m = m0 + ty * 4 + p * 2;
            atomicAdd(&g_init[m * Edim + n], v.x);
            atomicAdd(&g_init[(m + 1) * Edim + n], v.y);
        }
    }
}

// ============================================================
// K2: g_gx0 = x @ W_ih0^T + (b_ih0 + b_hh0), x gathered
//     [R9 64-tile form — measured 47.9us; M32 retile regressed twice]
// ============================================================
__global__ __launch_bounds__(256) void k_gx(const int* __restrict__ sent,
                                            const float* __restrict__ emb,
                                            const float* __restrict__ Wih0,
                                            const float* __restrict__ bih0,
                                            const float* __restrict__ bhh0) {
    __shared__ __align__(16) float As[32][64];
    __shared__ __align__(16) float Bs[32][128];
    const int tid = threadIdx.x;
    const int m0 = blockIdx.x * 64;
    const int tx = tid & 15, ty = tid >> 4;

    const int r = tid & 63;
    const int ha = tid >> 6;
    const int m = m0 + r;
    const int b = m / Sdim, s = m - b * Sdim;
    const float* Ap = (s == 0) ? (g_init + (size_t)b * Edim)
                               : (emb + (size_t)sent[b * Tdim + (s - 1)] * Edim);
    const int rb = tid & 127;
    const int hb = tid >> 7;
    const float* Bp = Wih0 + (size_t)rb * Edim;

    unsigned long long acc[8][2];
#pragma unroll
    for (int j = 0; j < 8; j++) { acc[j][0] = 0ull; acc[j][1] = 0ull; }

    for (int kc = 0; kc < 256; kc += 32) {
#pragma unroll
        for (int i = 0; i < 2; i++) {
            int seg = ha + i * 4;
            float4 v = *(const float4*)(Ap + kc + seg * 4);
            As[seg * 4 + 0][r] = v.x; As[seg * 4 + 1][r] = v.y;
            As[seg * 4 + 2][r] = v.z; As[seg * 4 + 3][r] = v.w;
        }
#pragma unroll
        for (int i = 0; i < 4; i++) {
            int seg = i * 2 + hb;
            float4 v = *(const float4*)(Bp + kc + seg * 4);
            Bs[seg * 4 + 0][rb] = v.x; Bs[seg * 4 + 1][rb] = v.y;
            Bs[seg * 4 + 2][rb] = v.z; Bs[seg * 4 + 3][rb] = v.w;
        }
        __syncthreads();
#pragma unroll 8
        for (int k = 0; k < 32; k++) {
            ulonglong2 a = *(const ulonglong2*)&As[k][ty * 4];
#pragma unroll
            for (int j = 0; j < 8; j++) {
                float bv = Bs[k][tx + j * 16];
                unsigned long long bd = pk2(bv, bv);
                acc[j][0] = fma2(a.x, bd, acc[j][0]);
                acc[j][1] = fma2(a.y, bd, acc[j][1]);
            }
        }
        __syncthreads();
    }
#pragma unroll
    for (int j = 0; j < 8; j++) {
        int n = tx + j * 16;
        float bias = bih0[n] + bhh0[n];
#pragma unroll
        for (int p = 0; p < 2; p++) {
            float2 v = up2(acc[j][p]);
            int mm = m0 + ty * 4 + p * 2;
            g_gx0[mm * G4 + n] = v.x + bias;
            g_gx0[(mm + 1) * G4 + n] = v.y + bias;
        }
    }
}

// ============================================================
// K3: fused 2-layer LSTM, 18 steps. 1 batch row per warp,
//     256 thr/block, 128 blocks. Gate math packed as f32x2
//     (2 accumulator chains instead of 4 scalar ones).
// ============================================================
__global__ __launch_bounds__(256) void k_lstm(const float* __restrict__ Whh0,
                                              const float* __restrict__ Wih1,
                                              const float* __restrict__ Whh1,
                                              const float* __restrict__ bih1,
                                              const float* __restrict__ bhh1) {
    __shared__ __align__(16) float W0[32 * 128];   // [k][j][q]  (q pairs adjacent)
    __shared__ __align__(16) float Wi1[32 * 128];
    __shared__ __align__(16) float Wh1[32 * 128];
    const int tid = threadIdx.x;

    for (int idx = tid; idx < 4096; idx += 256) {
        int k = idx >> 7, rem = idx & 127, j = rem >> 2, q = rem & 3;
        int src = (q * 32 + j) * 32 + k;
        W0[idx]  = Whh0[src];
        Wi1[idx] = Wih1[src];
        Wh1[idx] = Whh1[src];
    }
    __syncthreads();

    const int wid = tid >> 5, j = tid & 31;
    const int brow = blockIdx.x * 8 + wid;

    // packed layer-1 bias: (i,f) and (g,o)
    const unsigned long long b01p = pk2(bih1[j] + bhh1[j], bih1[32 + j] + bhh1[32 + j]);
    const unsigned long long b23p = pk2(bih1[64 + j] + bhh1[64 + j], bih1[96 + j] + bhh1[96 + j]);

    float hA = 0.f, cA = 0.f, hB = 0.f, cB = 0.f;

    float pre[4];
    {
        int m = brow * Sdim;
#pragma unroll
        for (int q = 0; q < 4; q++) pre[q] = g_gx0[m * G4 + q * 32 + j];
    }

    for (int s = 0; s < Sdim; s++) {
        unsigned long long gl01 = pk2(pre[0], pre[1]);
        unsigned long long gl23 = pk2(pre[2], pre[3]);
        if (s < Sdim - 1) {
            int m = brow * Sdim + s + 1;
#pragma unroll
            for (int q = 0; q < 4; q++) pre[q] = g_gx0[m * G4 + q * 32 + j];
        }
        // ---- layer 0: packed gate accumulate ----
#pragma unroll
        for (int k = 0; k < 32; k++) {
            ulonglong2 w = *(const ulonglong2*)&W0[k * 128 + j * 4];
            float h0 = __shfl_sync(0xffffffffu, hA, k);
            unsigned long long hd = pk2(h0, h0);
            gl01 = fma2(w.x, hd, gl01);
            gl23 = fma2(w.y, hd, gl23);
        }
        {
            float2 g01 = up2(gl01), g23 = up2(gl23);
            float ci = sigf(g01.x), cf = sigf(g01.y);
            float cg = tanhf(g23.x), co = sigf(g23.y);
            cA = cf * cA + ci * cg;
            hA = co * tanhf(cA);
        }
        // ---- layer 1: packed gate accumulate ----
        unsigned long long G01 = b01p, G23 = b23p;
#pragma unroll
        for (int k = 0; k < 32; k++) {
            ulonglong2 wi = *(const ulonglong2*)&Wi1[k * 128 + j * 4];
            ulonglong2 wh = *(const ulonglong2*)&Wh1[k * 128 + j * 4];
            float a0 = __shfl_sync(0xffffffffu, hA, k);
            float p0 = __shfl_sync(0xffffffffu, hB, k);
            unsigned long long ua = pk2(a0, a0);
            unsigned long long up = pk2(p0, p0);
            G01 = fma2(wi.x, ua, G01);
            G23 = fma2(wi.y, ua, G23);
            G01 = fma2(wh.x, up, G01);
            G23 = fma2(wh.y, up, G23);
        }
        {
            float2 g01 = up2(G01), g23 = up2(G23);
            float ci = sigf(g01.x), cf = sigf(g01.y);
            float cg = tanhf(g23.x), co = sigf(g23.y);
            cB = cf * cB + ci * cg;
            hB = co * tanhf(cB);
            g_h2cv[(size_t)(brow * Sdim + s) * 32 + j] = __float2half_rn(hB);
        }
    }
}

// ============================================================
// K4: mma.sync fp16 GEMM  out[18432, 14463] = h2 @ Wout^T + bias
//     [R8/R9 form, measured 223.6us] CTA tile 128x128, 8 warps, K=32.
// ============================================================
#define EPI_PITCH 136
#define K4_SMEM (128 * EPI_PITCH * 4)   // 69632; staging (16KB) overlays

__global__ __launch_bounds__(256, 2) void k_out_mma(const float* __restrict__ bout,
                                                    float* __restrict__ out) {
    extern __shared__ __align__(1024) char sm[];
    __half* As = (__half*)sm;                 // 8 KB: 128 rows x 64B, SW64
    __half* Bs = (__half*)(sm + 8192);        // 8 KB: 128 rows x 64B, SW64
    float*  epi = (float*)sm;                 // overlay, 128 x 136 floats

    const int tid = threadIdx.x;
    const int wid = tid >> 5, lane = tid & 31;
    const int n0 = blockIdx.x * 128;
    const int m0 = blockIdx.y * 128;

    // ---- stage A and B (512 int4 each; 2 per thread) ----
    const int4* Ag = (const int4*)(g_h2cv + (size_t)m0 * 32);
    const int4* Bg = (const int4*)(g_wcv + (size_t)n0 * 32);
#pragma unroll
    for (int it = 0; it < 2; it++) {
        int idx = tid + it * 256;
        int row = idx >> 2, u = idx & 3;
        uint32_t off = (uint32_t)(row * 64 + u * 16);
        *(int4*)((char*)As + SW64(off)) = Ag[idx];
        *(int4*)((char*)Bs + SW64(off)) = Bg[idx];
    }

    float bias_r[4];
#pragma unroll
    for (int c = 0; c < 4; c++) {
        int col = n0 + c * 32 + lane;
        bias_r[c] = (col < Vdim) ? bout[col] : 0.f;
    }
    __syncthreads();

    const uint32_t As_u = smem_u32(As);
    const uint32_t Bs_u = smem_u32(Bs);

    const int mwarp = (wid & 3) * 32;
    const int nwarp = (wid >> 2) * 64;
    const int rowa = lane & 15;
    const int sega = lane >> 4;

    float acc[2][8][4];
#pragma unroll
    for (int mf = 0; mf < 2; mf++)
#pragma unroll
        for (int j = 0; j < 8; j++)
#pragma unroll
            for (int q = 0; q < 4; q++) acc[mf][j][q] = 0.f;

#pragma unroll
    for (int p = 0; p < 2; p++) {                 // two k16 steps (K=32)
        uint32_t a[2][4];
#pragma unroll
        for (int mf = 0; mf < 2; mf++) {
            uint32_t off = (uint32_t)((mwarp + mf * 16 + rowa) * 64 + p * 32 + sega * 16);
            LDSM_X4(a[mf][0], a[mf][1], a[mf][2], a[mf][3], As_u + SW64(off));
        }
        uint32_t bfr[8][2];
#pragma unroll
        for (int nb = 0; nb < 4; nb++) {
            uint32_t r0, r1, r2, r3;
            uint32_t off = (uint32_t)((nwarp + nb * 16 + rowa) * 64 + p * 32 + sega * 16);
            LDSM_X4(r0, r1, r2, r3, Bs_u + SW64(off));
            bfr[nb * 2][0] = r0;     bfr[nb * 2][1] = r2;
            bfr[nb * 2 + 1][0] = r1; bfr[nb * 2 + 1][1] = r3;
        }
#pragma unroll
        for (int mf = 0; mf < 2; mf++)
#pragma unroll
            for (int j = 0; j < 8; j++)
                MMA16816F16(acc[mf][j], a[mf], bfr[j]);
    }

    // ---- single-pass epilogue: all accs -> smem, then coalesced stores ----
    __syncthreads();          // staging reads complete; overlay is safe
#pragma unroll
    for (int mf = 0; mf < 2; mf++)
#pragma unroll
        for (int j = 0; j < 8; j++) {
            int colb = nwarp + j * 8 + (lane & 3) * 2;
            int r0 = mwarp + mf * 16 + (lane >> 2);
            *(float2*)&epi[r0 * EPI_PITCH + colb] =
                make_float2(acc[mf][j][0], acc[mf][j][1]);
            *(float2*)&epi[(r0 + 8) * EPI_PITCH + colb] =
                make_float2(acc[mf][j][2], acc[mf][j][3]);
        }
    __syncthreads();

    const int rbase = wid * 16;
#pragma unroll
    for (int rr = 0; rr < 16; rr++) {
        size_t gro = (size_t)(m0 + rbase + rr) * Vdim + n0;
#pragma unroll
        for (int c = 0; c < 4; c++) {
            int col = c * 32 + lane;
            if (n0 + col < Vdim)
                out[gro + col] = epi[(rbase + rr) * EPI_PITCH + col] + bias_r[c];
        }
    }
}

// ============================================================
extern "C" void kernel_launch(void* const* d_in, const int* in_sizes, int n_in,
                              void* d_out, int out_size) {
    const float* graph = (const float*)d_in[0];
    const int*   sent  = (const int*)d_in[1];
    const float* Wg2e  = (const float*)d_in[2];
    const float* bg2e  = (const float*)d_in[3];
    const float* emb   = (const float*)d_in[4];
    const float* Wih0  = (const float*)d_in[5];
    const float* Whh0  = (const float*)d_in[6];
    const float* bih0  = (const float*)d_in[7];
    const float* bhh0  = (const float*)d_in[8];
    const float* Wih1  = (const float*)d_in[9];
    const float* Whh1  = (const float*)d_in[10];
    const float* bih1  = (const float*)d_in[11];
    const float* bhh1  = (const float*)d_in[12];
    const float* Wout  = (const float*)d_in[13];
    const float* bout  = (const float*)d_in[14];
    float* out = (float*)d_out;

    cudaFuncSetAttribute(k_out_mma, cudaFuncAttributeMaxDynamicSharedMemorySize,
                         K4_SMEM);

    k_init<<<WCVT_BLOCKS + INIT_BLOCKS, 256>>>(Wout, bg2e);
    k_proj<<<dim3(4, 16, 8), 256>>>(graph, Wg2e);
    k_gx<<<288, 256>>>(sent, emb, Wih0, bih0, bhh0);
    k_lstm<<<128, 256>>>(Whh0, Wih1, Whh1, bih1, bhh1);
    k_out_mma<<<dim3(113, 144), 256, K4_SMEM>>>(bout, out);
}

// round 12
// speedup vs baseline: 1.0946x; 1.0328x over previous
#include <cuda_runtime.h>
#include <cuda_fp16.h>
#include <cstdint>

#define Bsz 1024
#define Gdim 2048
#define Edim 256
#define Hdim 32
#define Vdim 14463
#define Vpad 14592   // 114 * 128
#define Tdim 18
#define Sdim 18      // last step's output is dropped
#define G4  128      // 4*H
#define Mtot (Bsz * Sdim)   // 18432

// k_init block layout
#define WCVT_BLOCKS 1824            // Vpad*32/256
#define ZERO_BLOCKS 512             // Bsz*G4/256
#define COMP_BLOCKS 64              // 128x2048 in 64x64 tiles
#define INIT_TOTAL (WCVT_BLOCKS + ZERO_BLOCKS + COMP_BLOCKS + 1)

// L2 (gxall) block layout
#define GXREST_BLOCKS 288           // Mtot/64
#define GX0_BLOCKS 128              // 16 m-tiles x split-K 8
#define GXALL_TOTAL (GXREST_BLOCKS + GX0_BLOCKS)

// ---- scratch (no cudaMalloc allowed) ----
__device__ float g_init[Bsz * Edim];                       // REUSED as W_comp[128][2048]
__device__ float g_bcomp[G4];                              // composite bias
__device__ float g_gx0[Bsz * Sdim * G4];                   // L0 input-gates precompute
__device__ __align__(16) __half g_h2cv[Mtot * 32];         // h2 rows: fp16, 32/row
__device__ __align__(16) __half g_wcv[(size_t)Vpad * 32];  // Wout rows: fp16, 32/row

// ================= packed f32x2 helpers =================
static __device__ __forceinline__ unsigned long long pk2(float lo, float hi) {
    unsigned long long r;
    asm("mov.b64 %0, {%1,%2};" : "=l"(r) : "f"(lo), "f"(hi));
    return r;
}
static __device__ __forceinline__ unsigned long long fma2(unsigned long long a,
                                                          unsigned long long b,
                                                          unsigned long long c) {
    unsigned long long d;
    asm("fma.rn.f32x2 %0, %1, %2, %3;" : "=l"(d) : "l"(a), "l"(b), "l"(c));
    return d;
}
static __device__ __forceinline__ float2 up2(unsigned long long v) {
    float2 f;
    asm("mov.b64 {%0,%1}, %2;" : "=f"(f.x), "=f"(f.y) : "l"(v));
    return f;
}
static __device__ __forceinline__ float sigf(float x) {
    return 1.0f / (1.0f + __expf(-x));
}

static __device__ __forceinline__ uint32_t smem_u32(const void* p) {
    uint32_t a;
    asm("{ .reg .u64 t; cvta.to.shared.u64 t, %1; cvt.u32.u64 %0, t; }" : "=r"(a) : "l"(p));
    return a;
}
#define SW64(o)  ((o) ^ (((o) >> 3) & 0x30))

#define LDSM_X4(r0, r1, r2, r3, addr) \
    asm volatile("ldmatrix.sync.aligned.m8n8.x4.shared.b16 {%0,%1,%2,%3}, [%4];" \
        : "=r"(r0), "=r"(r1), "=r"(r2), "=r"(r3) : "r"(addr))

#define MMA16816F16(c, a, b) \
    asm volatile("mma.sync.aligned.m16n8k16.row.col.f32.f16.f16.f32 " \
        "{%0,%1,%2,%3}, {%4,%5,%6,%7}, {%8,%9}, {%0,%1,%2,%3};" \
        : "+f"((c)[0]), "+f"((c)[1]), "+f"((c)[2]), "+f"((c)[3]) \
        : "r"((a)[0]), "r"((a)[1]), "r"((a)[2]), "r"((a)[3]), \
          "r"((b)[0]), "r"((b)[1]))

// ============================================================
// K1 (L1) k_init:
//   [0, WCVT)           : W_out -> fp16 convert+pad
//   [WCVT, +ZERO)       : zero g_gx0 rows with s==0 (split-K target)
//   [.., +COMP)         : W_comp = W_ih0 @ W_g2e   (64x64 tiles, K=256)
//   last block          : g_bcomp = W_ih0 @ b_g2e + b_ih0 + b_hh0
// ============================================================
__global__ __launch_bounds__(256) void k_init(const float* __restrict__ Wout,
                                              const float* __restrict__ Wg2e,
                                              const float* __restrict__ Wih0,
                                              const float* __restrict__ bg2e,
                                              const float* __restrict__ bih0,
                                              const float* __restrict__ bhh0) {
    __shared__ __align__(16) float As[32][64];
    __shared__ __align__(16) float Bs[32][64];
    const int tid = threadIdx.x;

    if (blockIdx.x < WCVT_BLOCKS) {
        int i = blockIdx.x * 256 + tid;
        int v = i >> 5, k = i & 31;
        float val = (v < Vdim) ? Wout[v * 32 + k] : 0.f;
        g_wcv[(size_t)v * 32 + k] = __float2half_rn(val);
        return;
    }
    if (blockIdx.x < WCVT_BLOCKS + ZERO_BLOCKS) {
        int i = (blockIdx.x - WCVT_BLOCKS) * 256 + tid;   // 0 .. 131071
        int b = i >> 7, n = i & 127;
        g_gx0[(b * Sdim) * G4 + n] = 0.f;
        return;
    }
    if (blockIdx.x < WCVT_BLOCKS + ZERO_BLOCKS + COMP_BLOCKS) {
        // ---- W_comp[g][c] = sum_e Wih0[g][e] * Wg2e[e][c] ----
        const int cb = blockIdx.x - (WCVT_BLOCKS + ZERO_BLOCKS);
        const int m0 = (cb >> 5) * 64;      // g dim (128)
        const int n0 = (cb & 31) * 64;      // c dim (2048)
        const int tx = tid & 15, ty = tid >> 4;
        const int r = tid & 63, h = tid >> 6;

        const float* Ap = Wih0 + (size_t)(m0 + r) * Edim;   // row g, k=e
        unsigned long long acc[4][2];
#pragma unroll
        for (int j = 0; j < 4; j++) { acc[j][0] = 0ull; acc[j][1] = 0ull; }

        for (int kc = 0; kc < Edim; kc += 32) {
#pragma unroll
            for (int i = 0; i < 2; i++) {
                int seg = h + i * 4;
                float4 va = *(const float4*)(Ap + kc + seg * 4);
                As[seg * 4 + 0][r] = va.x; As[seg * 4 + 1][r] = va.y;
                As[seg * 4 + 2][r] = va.z; As[seg * 4 + 3][r] = va.w;
            }
            // B: Bs[k][n] = Wg2e[kc+k][n0+n], contiguous in n
            {
                int ke = tid >> 4;              // 0..15
                int n4 = (tid & 15) * 4;
#pragma unroll
                for (int i = 0; i < 2; i++) {
                    int kk = ke + i * 16;
                    float4 v = *(const float4*)(Wg2e + (size_t)(kc + kk) * Gdim + n0 + n4);
                    Bs[kk][n4 + 0] = v.x; Bs[kk][n4 + 1] = v.y;
                    Bs[kk][n4 + 2] = v.z; Bs[kk][n4 + 3] = v.w;
                }
            }
            __syncthreads();
#pragma unroll 8
            for (int k = 0; k < 32; k++) {
                ulonglong2 a = *(const ulonglong2*)&As[k][ty * 4];
#pragma unroll
                for (int j = 0; j < 4; j++) {
                    float bv = Bs[k][tx + j * 16];
                    unsigned long long bd = pk2(bv, bv);
                    acc[j][0] = fma2(a.x, bd, acc[j][0]);
                    acc[j][1] = fma2(a.y, bd, acc[j][1]);
                }
            }
            __syncthreads();
        }
#pragma unroll
        for (int j = 0; j < 4; j++) {
            int n = n0 + tx + j * 16;
#pragma unroll
            for (int p = 0; p < 2; p++) {
                float2 v = up2(acc[j][p]);
                int m = m0 + ty * 4 + p * 2;
                g_init[m * Gdim + n] = v.x;           // g_init reused as W_comp
                g_init[(m + 1) * Gdim + n] = v.y;
            }
        }
        return;
    }
    // ---- bias_comp (1 block) ----
    if (tid < G4) {
        const float* w = Wih0 + (size_t)tid * Edim;
        float s = 0.f;
#pragma unroll 8
        for (int e = 0; e < Edim; e += 4) {
            float4 wv = *(const float4*)(w + e);
            float4 bv = *(const float4*)(bg2e + e);
            s += wv.x * bv.x + wv.y * bv.y + wv.z * bv.z + wv.w * bv.w;
        }
        g_bcomp[tid] = s + bih0[tid] + bhh0[tid];
    }
}

// ============================================================
// K2 (L2) k_gxall:
//   blocks [0, 288)   : gx_rest — emb-gathered rows (s>0), stores predicated
//   blocks [288, 416) : gx0 — split-K=8 GEMM graph @ W_comp^T, atomicAdd
// ============================================================
__global__ __launch_bounds__(256) void k_gxall(const int* __restrict__ sent,
                                               const float* __restrict__ emb,
                                               const float* __restrict__ Wih0,
                                               const float* __restrict__ bih0,
                                               const float* __restrict__ bhh0,
                                               const float* __restrict__ graph) {
    __shared__ __align__(16) float As[32][64];
    __shared__ __align__(16) float Bs[32][128];
    const int tid = threadIdx.x;
    const int tx = tid & 15, ty = tid >> 4;

    if (blockIdx.x < GXREST_BLOCKS) {
        // ================= gx_rest (R9 body + predicated stores) ============
        const int m0 = blockIdx.x * 64;
        const int r = tid & 63;
        const int ha = tid >> 6;
        const int m = m0 + r;
        const int b = m / Sdim, s = m - b * Sdim;
        const float* Ap = emb + (size_t)((s == 0) ? 0 : sent[b * Tdim + (s - 1)]) * Edim;
        const int rb = tid & 127;
        const int hb = tid >> 7;
        const float* Bp = Wih0 + (size_t)rb * Edim;

        unsigned long long acc[8][2];
#pragma unroll
        for (int j = 0; j < 8; j++) { acc[j][0] = 0ull; acc[j][1] = 0ull; }

        for (int kc = 0; kc < 256; kc += 32) {
#pragma unroll
            for (int i = 0; i < 2; i++) {
                int seg = ha + i * 4;
                float4 v = *(const float4*)(Ap + kc + seg * 4);
                As[seg * 4 + 0][r] = v.x; As[seg * 4 + 1][r] = v.y;
                As[seg * 4 + 2][r] = v.z; As[seg * 4 + 3][r] = v.w;
            }
#pragma unroll
            for (int i = 0; i < 4; i++) {
                int seg = i * 2 + hb;
                float4 v = *(const float4*)(Bp + kc + seg * 4);
                Bs[seg * 4 + 0][rb] = v.x; Bs[seg * 4 + 1][rb] = v.y;
                Bs[seg * 4 + 2][rb] = v.z; Bs[seg * 4 + 3][rb] = v.w;
            }
            __syncthreads();
#pragma unroll 8
            for (int k = 0; k < 32; k++) {
                ulonglong2 a = *(const ulonglong2*)&As[k][ty * 4];
#pragma unroll
                for (int j = 0; j < 8; j++) {
                    float bv = Bs[k][tx + j * 16];
                    unsigned long long bd = pk2(bv, bv);
                    acc[j][0] = fma2(a.x, bd, acc[j][0]);
                    acc[j][1] = fma2(a.y, bd, acc[j][1]);
                }
            }
            __syncthreads();
        }
#pragma unroll
        for (int j = 0; j < 8; j++) {
            int n = tx + j * 16;
            float bias = bih0[n] + bhh0[n];
#pragma unroll
            for (int p = 0; p < 2; p++) {
                float2 v = up2(acc[j][p]);
                int mm = m0 + ty * 4 + p * 2;
                if (mm % Sdim != 0)       g_gx0[mm * G4 + n] = v.x + bias;
                if ((mm + 1) % Sdim != 0) g_gx0[(mm + 1) * G4 + n] = v.y + bias;
            }
        }
    } else {
        // ================= gx0: graph[1024,2048] @ W_comp[128,2048]^T =======
        const int gb = blockIdx.x - GXREST_BLOCKS;
        const int m0b = (gb & 15) * 64;          // batch-row tile
        const int kbase = (gb >> 4) * 256;       // split-K chunk

        const int r = tid & 63;
        const int ha = tid >> 6;
        const float* Ap = graph + (size_t)(m0b + r) * Gdim + kbase;
        const int rb = tid & 127;
        const int hb = tid >> 7;
        const float* Bp = g_init + (size_t)rb * Gdim + kbase;   // W_comp rows

        unsigned long long acc[8][2];
#pragma unroll
        for (int j = 0; j < 8; j++) { acc[j][0] = 0ull; acc[j][1] = 0ull; }

        for (int kc = 0; kc < 256; kc += 32) {
#pragma unroll
            for (int i = 0; i < 2; i++) {
                int seg = ha + i * 4;
                float4 v = *(const float4*)(Ap + kc + seg * 4);
                As[seg * 4 + 0][r] = v.x; As[seg * 4 + 1][r] = v.y;
                As[seg * 4 + 2][r] = v.z; As[seg * 4 + 3][r] = v.w;
            }
#pragma unroll
            for (int i = 0; i < 4; i++) {
                int seg = i * 2 + hb;
                float4 v = *(const float4*)(Bp + kc + seg * 4);
                Bs[seg * 4 + 0][rb] = v.x; Bs[seg * 4 + 1][rb] = v.y;
                Bs[seg * 4 + 2][rb] = v.z; Bs[seg * 4 + 3][rb] = v.w;
            }
            __syncthreads();
#pragma unroll 8
            for (int k = 0; k < 32; k++) {
                ulonglong2 a = *(const ulonglong2*)&As[k][ty * 4];
#pragma unroll
                for (int j = 0; j < 8; j++) {
                    float bv = Bs[k][tx + j * 16];
                    unsigned long long bd = pk2(bv, bv);
                    acc[j][0] = fma2(a.x, bd, acc[j][0]);
                    acc[j][1] = fma2(a.y, bd, acc[j][1]);
                }
            }
            __syncthreads();
        }
#pragma unroll
        for (int j = 0; j < 8; j++) {
            int n = tx + j * 16;
#pragma unroll
            for (int p = 0; p < 2; p++) {
                float2 v = up2(acc[j][p]);
                int b = m0b + ty * 4 + p * 2;
                atomicAdd(&g_gx0[(b * Sdim) * G4 + n], v.x);
                atomicAdd(&g_gx0[((b + 1) * Sdim) * G4 + n], v.y);
            }
        }
    }
}

// ============================================================
// K3: fused 2-layer LSTM, 18 steps. 1 row/warp, f32x2-packed gates.
//     s==0 gx row gets the composite bias added here.
// ============================================================
__global__ __launch_bounds__(256) void k_lstm(const float* __restrict__ Whh0,
                                              const float* __restrict__ Wih1,
                                              const float* __restrict__ Whh1,
                                              const float* __restrict__ bih1,
                                              const float* __restrict__ bhh1) {
    __shared__ __align__(16) float W0[32 * 128];   // [k][j][q]
    __shared__ __align__(16) float Wi1[32 * 128];
    __shared__ __align__(16) float Wh1[32 * 128];
    const int tid = threadIdx.x;

    for (int idx = tid; idx < 4096; idx += 256) {
        int k = idx >> 7, rem = idx & 127, j = rem >> 2, q = rem & 3;
        int src = (q * 32 + j) * 32 + k;
        W0[idx]  = Whh0[src];
        Wi1[idx] = Wih1[src];
        Wh1[idx] = Whh1[src];
    }
    __syncthreads();

    const int wid = tid >> 5, j = tid & 31;
    const int brow = blockIdx.x * 8 + wid;

    const unsigned long long b01p = pk2(bih1[j] + bhh1[j], bih1[32 + j] + bhh1[32 + j]);
    const unsigned long long b23p = pk2(bih1[64 + j] + bhh1[64 + j], bih1[96 + j] + bhh1[96 + j]);

    float hA = 0.f, cA = 0.f, hB = 0.f, cB = 0.f;

    float pre[4];
    {
        int m = brow * Sdim;
#pragma unroll
        for (int q = 0; q < 4; q++)
            pre[q] = g_gx0[m * G4 + q * 32 + j] + g_bcomp[q * 32 + j];
    }

    for (int s = 0; s < Sdim; s++) {
        unsigned long long gl01 = pk2(pre[0], pre[1]);
        unsigned long long gl23 = pk2(pre[2], pre[3]);
        if (s < Sdim - 1) {
            int m = brow * Sdim + s + 1;
#pragma unroll
            for (int q = 0; q < 4; q++) pre[q] = g_gx0[m * G4 + q * 32 + j];
        }
        // ---- layer 0 ----
#pragma unroll
        for (int k = 0; k < 32; k++) {
            ulonglong2 w = *(const ulonglong2*)&W0[k * 128 + j * 4];
            float h0 = __shfl_sync(0xffffffffu, hA, k);
            unsigned long long hd = pk2(h0, h0);
            gl01 = fma2(w.x, hd, gl01);
            gl23 = fma2(w.y, hd, gl23);
        }
        {
            float2 g01 = up2(gl01), g23 = up2(gl23);
            float ci = sigf(g01.x), cf = sigf(g01.y);
            float cg = tanhf(g23.x), co = sigf(g23.y);
            cA = cf * cA + ci * cg;
            hA = co * tanhf(cA);
        }
        // ---- layer 1 ----
        unsigned long long G01 = b01p, G23 = b23p;
#pragma unroll
        for (int k = 0; k < 32; k++) {
            ulonglong2 wi = *(const ulonglong2*)&Wi1[k * 128 + j * 4];
            ulonglong2 wh = *(const ulonglong2*)&Wh1[k * 128 + j * 4];
            float a0 = __shfl_sync(0xffffffffu, hA, k);
            float p0 = __shfl_sync(0xffffffffu, hB, k);
            unsigned long long ua = pk2(a0, a0);
            unsigned long long up = pk2(p0, p0);
            G01 = fma2(wi.x, ua, G01);
            G23 = fma2(wi.y, ua, G23);
            G01 = fma2(wh.x, up, G01);
            G23 = fma2(wh.y, up, G23);
        }
        {
            float2 g01 = up2(G01), g23 = up2(G23);
            float ci = sigf(g01.x), cf = sigf(g01.y);
            float cg = tanhf(g23.x), co = sigf(g23.y);
            cB = cf * cB + ci * cg;
            hB = co * tanhf(cB);
            g_h2cv[(size_t)(brow * Sdim + s) * 32 + j] = __float2half_rn(hB);
        }
    }
}

// ============================================================
// K4: mma.sync fp16 GEMM  out[18432, 14463] = h2 @ Wout^T + bias
//     [R8/R9 form, measured 223.6us]
// ============================================================
#define EPI_PITCH 136
#define K4_SMEM (128 * EPI_PITCH * 4)   // 69632

__global__ __launch_bounds__(256, 2) void k_out_mma(const float* __restrict__ bout,
                                                    float* __restrict__ out) {
    extern __shared__ __align__(1024) char sm[];
    __half* As = (__half*)sm;
    __half* Bs = (__half*)(sm + 8192);
    float*  epi = (float*)sm;

    const int tid = threadIdx.x;
    const int wid = tid >> 5, lane = tid & 31;
    const int n0 = blockIdx.x * 128;
    const int m0 = blockIdx.y * 128;

    const int4* Ag = (const int4*)(g_h2cv + (size_t)m0 * 32);
    const int4* Bg = (const int4*)(g_wcv + (size_t)n0 * 32);
#pragma unroll
    for (int it = 0; it < 2; it++) {
        int idx = tid + it * 256;
        int row = idx >> 2, u = idx & 3;
        uint32_t off = (uint32_t)(row * 64 + u * 16);
        *(int4*)((char*)As + SW64(off)) = Ag[idx];
        *(int4*)((char*)Bs + SW64(off)) = Bg[idx];
    }

    float bias_r[4];
#pragma unroll
    for (int c = 0; c < 4; c++) {
        int col = n0 + c * 32 + lane;
        bias_r[c] = (col < Vdim) ? bout[col] : 0.f;
    }
    __syncthreads();

    const uint32_t As_u = smem_u32(As);
    const uint32_t Bs_u = smem_u32(Bs);

    const int mwarp = (wid & 3) * 32;
    const int nwarp = (wid >> 2) * 64;
    const int rowa = lane & 15;
    const int sega = lane >> 4;

    float acc[2][8][4];
#pragma unroll
    for (int mf = 0; mf < 2; mf++)
#pragma unroll
        for (int j = 0; j < 8; j++)
#pragma unroll
            for (int q = 0; q < 4; q++) acc[mf][j][q] = 0.f;

#pragma unroll
    for (int p = 0; p < 2; p++) {
        uint32_t a[2][4];
#pragma unroll
        for (int mf = 0; mf < 2; mf++) {
            uint32_t off = (uint32_t)((mwarp + mf * 16 + rowa) * 64 + p * 32 + sega * 16);
            LDSM_X4(a[mf][0], a[mf][1], a[mf][2], a[mf][3], As_u + SW64(off));
        }
        uint32_t bfr[8][2];
#pragma unroll
        for (int nb = 0; nb < 4; nb++) {
            uint32_t r0, r1, r2, r3;
            uint32_t off = (uint32_t)((nwarp + nb * 16 + rowa) * 64 + p * 32 + sega * 16);
            LDSM_X4(r0, r1, r2, r3, Bs_u + SW64(off));
            bfr[nb * 2][0] = r0;     bfr[nb * 2][1] = r2;
            bfr[nb * 2 + 1][0] = r1; bfr[nb * 2 + 1][1] = r3;
        }
#pragma unroll
        for (int mf = 0; mf < 2; mf++)
#pragma unroll
            for (int j = 0; j < 8; j++)
                MMA16816F16(acc[mf][j], a[mf], bfr[j]);
    }

    __syncthreads();
#pragma unroll
    for (int mf = 0; mf < 2; mf++)
#pragma unroll
        for (int j = 0; j < 8; j++) {
            int colb = nwarp + j * 8 + (lane & 3) * 2;
            int r0 = mwarp + mf * 16 + (lane >> 2);
            *(float2*)&epi[r0 * EPI_PITCH + colb] =
                make_float2(acc[mf][j][0], acc[mf][j][1]);
            *(float2*)&epi[(r0 + 8) * EPI_PITCH + colb] =
                make_float2(acc[mf][j][2], acc[mf][j][3]);
        }
    __syncthreads();

    const int rbase = wid * 16;
#pragma unroll
    for (int rr = 0; rr < 16; rr++) {
        size_t gro = (size_t)(m0 + rbase + rr) * Vdim + n0;
#pragma unroll
        for (int c = 0; c < 4; c++) {
            int col = c * 32 + lane;
            if (n0 + col < Vdim)
                out[gro + col] = epi[(rbase + rr) * EPI_PITCH + col] + bias_r[c];
        }
    }
}

// ============================================================
extern "C" void kernel_launch(void* const* d_in, const int* in_sizes, int n_in,
                              void* d_out, int out_size) {
    const float* graph = (const float*)d_in[0];
    const int*   sent  = (const int*)d_in[1];
    const float* Wg2e  = (const float*)d_in[2];
    const float* bg2e  = (const float*)d_in[3];
    const float* emb   = (const float*)d_in[4];
    const float* Wih0  = (const float*)d_in[5];
    const float* Whh0  = (const float*)d_in[6];
    const float* bih0  = (const float*)d_in[7];
    const float* bhh0  = (const float*)d_in[8];
    const float* Wih1  = (const float*)d_in[9];
    const float* Whh1  = (const float*)d_in[10];
    const float* bih1  = (const float*)d_in[11];
    const float* bhh1  = (const float*)d_in[12];
    const float* Wout  = (const float*)d_in[13];
    const float* bout  = (const float*)d_in[14];
    float* out = (float*)d_out;

    cudaFuncSetAttribute(k_out_mma, cudaFuncAttributeMaxDynamicSharedMemorySize,
                         K4_SMEM);

    k_init<<<INIT_TOTAL, 256>>>(Wout, Wg2e, Wih0, bg2e, bih0, bhh0);
    k_gxall<<<GXALL_TOTAL, 256>>>(sent, emb, Wih0, bih0, bhh0, graph);
    k_lstm<<<128, 256>>>(Whh0, Wih1, Whh1, bih1, bhh1);
    k_out_mma<<<dim3(113, 144), 256, K4_SMEM>>>(bout, out);
}

// round 13
// speedup vs baseline: 1.0961x; 1.0013x over previous
#include <cuda_runtime.h>
#include <cuda_fp16.h>
#include <cstdint>

#define Bsz 1024
#define Gdim 2048
#define Edim 256
#define Hdim 32
#define Vdim 14463
#define Vpad 14592   // 114 * 128
#define Tdim 18
#define Sdim 18      // last step's output is dropped
#define G4  128      // 4*H
#define Mtot (Bsz * Sdim)   // 18432

// k_init block layout
#define WCVT_BLOCKS 1824            // Vpad*32/256
#define ZERO_BLOCKS 512             // Bsz*G4/256
#define COMP_BLOCKS 64              // 128x2048 in 64x64 tiles
#define INIT_TOTAL (WCVT_BLOCKS + ZERO_BLOCKS + COMP_BLOCKS + 1)

// L2 (gxall) block layout
#define GXREST_BLOCKS 288           // Mtot/64
#define GX0_BLOCKS 128              // 16 m-tiles x split-K 8
#define GXALL_TOTAL (GXREST_BLOCKS + GX0_BLOCKS)

// ---- scratch (no cudaMalloc allowed) ----
__device__ float g_init[Bsz * Edim];                       // REUSED as W_comp[128][2048]
__device__ float g_bcomp[G4];                              // composite bias
__device__ float g_gx0[Bsz * Sdim * G4];                   // L0 input-gates precompute
__device__ __align__(16) __half g_h2cv[Mtot * 32];         // h2 rows: fp16, 32/row
__device__ __align__(16) __half g_wcv[(size_t)Vpad * 32];  // Wout rows: fp16, 32/row

// ================= packed f32x2 helpers =================
static __device__ __forceinline__ unsigned long long pk2(float lo, float hi) {
    unsigned long long r;
    asm("mov.b64 %0, {%1,%2};" : "=l"(r) : "f"(lo), "f"(hi));
    return r;
}
static __device__ __forceinline__ unsigned long long fma2(unsigned long long a,
                                                          unsigned long long b,
                                                          unsigned long long c) {
    unsigned long long d;
    asm("fma.rn.f32x2 %0, %1, %2, %3;" : "=l"(d) : "l"(a), "l"(b), "l"(c));
    return d;
}
static __device__ __forceinline__ unsigned long long add2(unsigned long long a,
                                                          unsigned long long b) {
    unsigned long long d;
    asm("add.rn.f32x2 %0, %1, %2;" : "=l"(d) : "l"(a), "l"(b));
    return d;
}
static __device__ __forceinline__ float2 up2(unsigned long long v) {
    float2 f;
    asm("mov.b64 {%0,%1}, %2;" : "=f"(f.x), "=f"(f.y) : "l"(v));
    return f;
}
static __device__ __forceinline__ float sigf(float x) {
    return 1.0f / (1.0f + __expf(-x));
}
static __device__ __forceinline__ float tanhap(float x) {
    float r;
    asm("tanh.approx.f32 %0, %1;" : "=f"(r) : "f"(x));
    return r;
}

static __device__ __forceinline__ uint32_t smem_u32(const void* p) {
    uint32_t a;
    asm("{ .reg .u64 t; cvta.to.shared.u64 t, %1; cvt.u32.u64 %0, t; }" : "=r"(a) : "l"(p));
    return a;
}
#define SW64(o)  ((o) ^ (((o) >> 3) & 0x30))

#define LDSM_X4(r0, r1, r2, r3, addr) \
    asm volatile("ldmatrix.sync.aligned.m8n8.x4.shared.b16 {%0,%1,%2,%3}, [%4];" \
        : "=r"(r0), "=r"(r1), "=r"(r2), "=r"(r3) : "r"(addr))

#define MMA16816F16(c, a, b) \
    asm volatile("mma.sync.aligned.m16n8k16.row.col.f32.f16.f16.f32 " \
        "{%0,%1,%2,%3}, {%4,%5,%6,%7}, {%8,%9}, {%0,%1,%2,%3};" \
        : "+f"((c)[0]), "+f"((c)[1]), "+f"((c)[2]), "+f"((c)[3]) \
        : "r"((a)[0]), "r"((a)[1]), "r"((a)[2]), "r"((a)[3]), \
          "r"((b)[0]), "r"((b)[1]))

// ============================================================
// K1 (L1) k_init:
//   [0, WCVT)           : W_out -> fp16 convert+pad
//   [WCVT, +ZERO)       : zero g_gx0 rows with s==0 (split-K target)
//   [.., +COMP)         : W_comp = W_ih0 @ W_g2e   (64x64 tiles, K=256)
//   last block          : g_bcomp = W_ih0 @ b_g2e + b_ih0 + b_hh0
// ============================================================
__global__ __launch_bounds__(256) void k_init(const float* __restrict__ Wout,
                                              const float* __restrict__ Wg2e,
                                              const float* __restrict__ Wih0,
                                              const float* __restrict__ bg2e,
                                              const float* __restrict__ bih0,
                                              const float* __restrict__ bhh0) {
    __shared__ __align__(16) float As[32][64];
    __shared__ __align__(16) float Bs[32][64];
    const int tid = threadIdx.x;

    if (blockIdx.x < WCVT_BLOCKS) {
        int i = blockIdx.x * 256 + tid;
        int v = i >> 5, k = i & 31;
        float val = (v < Vdim) ? Wout[v * 32 + k] : 0.f;
        g_wcv[(size_t)v * 32 + k] = __float2half_rn(val);
        return;
    }
    if (blockIdx.x < WCVT_BLOCKS + ZERO_BLOCKS) {
        int i = (blockIdx.x - WCVT_BLOCKS) * 256 + tid;   // 0 .. 131071
        int b = i >> 7, n = i & 127;
        g_gx0[(b * Sdim) * G4 + n] = 0.f;
        return;
    }
    if (blockIdx.x < WCVT_BLOCKS + ZERO_BLOCKS + COMP_BLOCKS) {
        // ---- W_comp[g][c] = sum_e Wih0[g][e] * Wg2e[e][c] ----
        const int cb = blockIdx.x - (WCVT_BLOCKS + ZERO_BLOCKS);
        const int m0 = (cb >> 5) * 64;      // g dim (128)
        const int n0 = (cb & 31) * 64;      // c dim (2048)
        const int tx = tid & 15, ty = tid >> 4;
        const int r = tid & 63, h = tid >> 6;

        const float* Ap = Wih0 + (size_t)(m0 + r) * Edim;   // row g, k=e
        unsigned long long acc[4][2];
#pragma unroll
        for (int j = 0; j < 4; j++) { acc[j][0] = 0ull; acc[j][1] = 0ull; }

        for (int kc = 0; kc < Edim; kc += 32) {
#pragma unroll
            for (int i = 0; i < 2; i++) {
                int seg = h + i * 4;
                float4 va = *(const float4*)(Ap + kc + seg * 4);
                As[seg * 4 + 0][r] = va.x; As[seg * 4 + 1][r] = va.y;
                As[seg * 4 + 2][r] = va.z; As[seg * 4 + 3][r] = va.w;
            }
            {
                int ke = tid >> 4;              // 0..15
                int n4 = (tid & 15) * 4;
#pragma unroll
                for (int i = 0; i < 2; i++) {
                    int kk = ke + i * 16;
                    float4 v = *(const float4*)(Wg2e + (size_t)(kc + kk) * Gdim + n0 + n4);
                    Bs[kk][n4 + 0] = v.x; Bs[kk][n4 + 1] = v.y;
                    Bs[kk][n4 + 2] = v.z; Bs[kk][n4 + 3] = v.w;
                }
            }
            __syncthreads();
#pragma unroll 8
            for (int k = 0; k < 32; k++) {
                ulonglong2 a = *(const ulonglong2*)&As[k][ty * 4];
#pragma unroll
                for (int j = 0; j < 4; j++) {
                    float bv = Bs[k][tx + j * 16];
                    unsigned long long bd = pk2(bv, bv);
                    acc[j][0] = fma2(a.x, bd, acc[j][0]);
                    acc[j][1] = fma2(a.y, bd, acc[j][1]);
                }
            }
            __syncthreads();
        }
#pragma unroll
        for (int j = 0; j < 4; j++) {
            int n = n0 + tx + j * 16;
#pragma unroll
            for (int p = 0; p < 2; p++) {
                float2 v = up2(acc[j][p]);
                int m = m0 + ty * 4 + p * 2;
                g_init[m * Gdim + n] = v.x;           // g_init reused as W_comp
                g_init[(m + 1) * Gdim + n] = v.y;
            }
        }
        return;
    }
    // ---- bias_comp (1 block) ----
    if (tid < G4) {
        const float* w = Wih0 + (size_t)tid * Edim;
        float s = 0.f;
#pragma unroll 8
        for (int e = 0; e < Edim; e += 4) {
            float4 wv = *(const float4*)(w + e);
            float4 bv = *(const float4*)(bg2e + e);
            s += wv.x * bv.x + wv.y * bv.y + wv.z * bv.z + wv.w * bv.w;
        }
        g_bcomp[tid] = s + bih0[tid] + bhh0[tid];
    }
}

// ============================================================
// K2 (L2) k_gxall:
//   blocks [0, 288)   : gx_rest — emb-gathered rows (s>0), stores predicated
//   blocks [288, 416) : gx0 — split-K=8 GEMM graph @ W_comp^T, atomicAdd
// ============================================================
__global__ __launch_bounds__(256) void k_gxall(const int* __restrict__ sent,
                                               const float* __restrict__ emb,
                                               const float* __restrict__ Wih0,
                                               const float* __restrict__ bih0,
                                               const float* __restrict__ bhh0,
                                               const float* __restrict__ graph) {
    __shared__ __align__(16) float As[32][64];
    __shared__ __align__(16) float Bs[32][128];
    const int tid = threadIdx.x;
    const int tx = tid & 15, ty = tid >> 4;

    if (blockIdx.x < GXREST_BLOCKS) {
        const int m0 = blockIdx.x * 64;
        const int r = tid & 63;
        const int ha = tid >> 6;
        const int m = m0 + r;
        const int b = m / Sdim, s = m - b * Sdim;
        const float* Ap = emb + (size_t)((s == 0) ? 0 : sent[b * Tdim + (s - 1)]) * Edim;
        const int rb = tid & 127;
        const int hb = tid >> 7;
        const float* Bp = Wih0 + (size_t)rb * Edim;

        unsigned long long acc[8][2];
#pragma unroll
        for (int j = 0; j < 8; j++) { acc[j][0] = 0ull; acc[j][1] = 0ull; }

        for (int kc = 0; kc < 256; kc += 32) {
#pragma unroll
            for (int i = 0; i < 2; i++) {
                int seg = ha + i * 4;
                float4 v = *(const float4*)(Ap + kc + seg * 4);
                As[seg * 4 + 0][r] = v.x; As[seg * 4 + 1][r] = v.y;
                As[seg * 4 + 2][r] = v.z; As[seg * 4 + 3][r] = v.w;
            }
#pragma unroll
            for (int i = 0; i < 4; i++) {
                int seg = i * 2 + hb;
                float4 v = *(const float4*)(Bp + kc + seg * 4);
                Bs[seg * 4 + 0][rb] = v.x; Bs[seg * 4 + 1][rb] = v.y;
                Bs[seg * 4 + 2][rb] = v.z; Bs[seg * 4 + 3][rb] = v.w;
            }
            __syncthreads();
#pragma unroll 8
            for (int k = 0; k < 32; k++) {
                ulonglong2 a = *(const ulonglong2*)&As[k][ty * 4];
#pragma unroll
                for (int j = 0; j < 8; j++) {
                    float bv = Bs[k][tx + j * 16];
                    unsigned long long bd = pk2(bv, bv);
                    acc[j][0] = fma2(a.x, bd, acc[j][0]);
                    acc[j][1] = fma2(a.y, bd, acc[j][1]);
                }
            }
            __syncthreads();
        }
#pragma unroll
        for (int j = 0; j < 8; j++) {
            int n = tx + j * 16;
            float bias = bih0[n] + bhh0[n];
#pragma unroll
            for (int p = 0; p < 2; p++) {
                float2 v = up2(acc[j][p]);
                int mm = m0 + ty * 4 + p * 2;
                if (mm % Sdim != 0)       g_gx0[mm * G4 + n] = v.x + bias;
                if ((mm + 1) % Sdim != 0) g_gx0[(mm + 1) * G4 + n] = v.y + bias;
            }
        }
    } else {
        const int gb = blockIdx.x - GXREST_BLOCKS;
        const int m0b = (gb & 15) * 64;          // batch-row tile
        const int kbase = (gb >> 4) * 256;       // split-K chunk

        const int r = tid & 63;
        const int ha = tid >> 6;
        const float* Ap = graph + (size_t)(m0b + r) * Gdim + kbase;
        const int rb = tid & 127;
        const int hb = tid >> 7;
        const float* Bp = g_init + (size_t)rb * Gdim + kbase;   // W_comp rows

        unsigned long long acc[8][2];
#pragma unroll
        for (int j = 0; j < 8; j++) { acc[j][0] = 0ull; acc[j][1] = 0ull; }

        for (int kc = 0; kc < 256; kc += 32) {
#pragma unroll
            for (int i = 0; i < 2; i++) {
                int seg = ha + i * 4;
                float4 v = *(const float4*)(Ap + kc + seg * 4);
                As[seg * 4 + 0][r] = v.x; As[seg * 4 + 1][r] = v.y;
                As[seg * 4 + 2][r] = v.z; As[seg * 4 + 3][r] = v.w;
            }
#pragma unroll
            for (int i = 0; i < 4; i++) {
                int seg = i * 2 + hb;
                float4 v = *(const float4*)(Bp + kc + seg * 4);
                Bs[seg * 4 + 0][rb] = v.x; Bs[seg * 4 + 1][rb] = v.y;
                Bs[seg * 4 + 2][rb] = v.z; Bs[seg * 4 + 3][rb] = v.w;
            }
            __syncthreads();
#pragma unroll 8
            for (int k = 0; k < 32; k++) {
                ulonglong2 a = *(const ulonglong2*)&As[k][ty * 4];
#pragma unroll
                for (int j = 0; j < 8; j++) {
                    float bv = Bs[k][tx + j * 16];
                    unsigned long long bd = pk2(bv, bv);
                    acc[j][0] = fma2(a.x, bd, acc[j][0]);
                    acc[j][1] = fma2(a.y, bd, acc[j][1]);
                }
            }
            __syncthreads();
        }
#pragma unroll
        for (int j = 0; j < 8; j++) {
            int n = tx + j * 16;
#pragma unroll
            for (int p = 0; p < 2; p++) {
                float2 v = up2(acc[j][p]);
                int b = m0b + ty * 4 + p * 2;
                atomicAdd(&g_gx0[(b * Sdim) * G4 + n], v.x);
                atomicAdd(&g_gx0[((b + 1) * Sdim) * G4 + n], v.y);
            }
        }
    }
}

// ============================================================
// K3: fused 2-layer LSTM, 18 steps. 1 row/warp.
//     R13: split accumulation chains (even/odd k, wi/wh) to cut the
//     serial fma2 dependency depth 32->16 / 64->16, and MUFU tanh
//     (tanh.approx.f32) instead of libdevice tanhf on the critical path.
// ============================================================
__global__ __launch_bounds__(256) void k_lstm(const float* __restrict__ Whh0,
                                              const float* __restrict__ Wih1,
                                              const float* __restrict__ Whh1,
                                              const float* __restrict__ bih1,
                                              const float* __restrict__ bhh1) {
    __shared__ __align__(16) float W0[32 * 128];   // [k][j][q]
    __shared__ __align__(16) float Wi1[32 * 128];
    __shared__ __align__(16) float Wh1[32 * 128];
    const int tid = threadIdx.x;

    for (int idx = tid; idx < 4096; idx += 256) {
        int k = idx >> 7, rem = idx & 127, j = rem >> 2, q = rem & 3;
        int src = (q * 32 + j) * 32 + k;
        W0[idx]  = Whh0[src];
        Wi1[idx] = Wih1[src];
        Wh1[idx] = Whh1[src];
    }
    __syncthreads();

    const int wid = tid >> 5, j = tid & 31;
    const int brow = blockIdx.x * 8 + wid;

    const unsigned long long b01p = pk2(bih1[j] + bhh1[j], bih1[32 + j] + bhh1[32 + j]);
    const unsigned long long b23p = pk2(bih1[64 + j] + bhh1[64 + j], bih1[96 + j] + bhh1[96 + j]);

    float hA = 0.f, cA = 0.f, hB = 0.f, cB = 0.f;

    float pre[4];
    {
        int m = brow * Sdim;
#pragma unroll
        for (int q = 0; q < 4; q++)
            pre[q] = g_gx0[m * G4 + q * 32 + j] + g_bcomp[q * 32 + j];
    }

    for (int s = 0; s < Sdim; s++) {
        unsigned long long l01a = pk2(pre[0], pre[1]), l01b = 0ull;
        unsigned long long l23a = pk2(pre[2], pre[3]), l23b = 0ull;
        if (s < Sdim - 1) {
            int m = brow * Sdim + s + 1;
#pragma unroll
            for (int q = 0; q < 4; q++) pre[q] = g_gx0[m * G4 + q * 32 + j];
        }
        // ---- layer 0: 2-way split chains (depth 16) ----
#pragma unroll
        for (int k = 0; k < 32; k += 2) {
            ulonglong2 w0 = *(const ulonglong2*)&W0[k * 128 + j * 4];
            ulonglong2 w1 = *(const ulonglong2*)&W0[(k + 1) * 128 + j * 4];
            float h0 = __shfl_sync(0xffffffffu, hA, k);
            float h1 = __shfl_sync(0xffffffffu, hA, k + 1);
            unsigned long long hd0 = pk2(h0, h0);
            unsigned long long hd1 = pk2(h1, h1);
            l01a = fma2(w0.x, hd0, l01a);
            l23a = fma2(w0.y, hd0, l23a);
            l01b = fma2(w1.x, hd1, l01b);
            l23b = fma2(w1.y, hd1, l23b);
        }
        {
            float2 g01 = up2(add2(l01a, l01b));
            float2 g23 = up2(add2(l23a, l23b));
            float ci = sigf(g01.x), cf = sigf(g01.y);
            float cg = tanhap(g23.x), co = sigf(g23.y);
            cA = cf * cA + ci * cg;
            hA = co * tanhap(cA);
        }
        // ---- layer 1: 4-way split chains (wi/wh x even/odd, depth 16) ----
        unsigned long long i01a = b01p, i01b = 0ull, i23a = b23p, i23b = 0ull;
        unsigned long long h01a = 0ull, h01b = 0ull, h23a = 0ull, h23b = 0ull;
#pragma unroll
        for (int k = 0; k < 32; k += 2) {
            ulonglong2 wi0 = *(const ulonglong2*)&Wi1[k * 128 + j * 4];
            ulonglong2 wi1 = *(const ulonglong2*)&Wi1[(k + 1) * 128 + j * 4];
            ulonglong2 wh0 = *(const ulonglong2*)&Wh1[k * 128 + j * 4];
            ulonglong2 wh1 = *(const ulonglong2*)&Wh1[(k + 1) * 128 + j * 4];
            float a0 = __shfl_sync(0xffffffffu, hA, k);
            float a1 = __shfl_sync(0xffffffffu, hA, k + 1);
            float p0 = __shfl_sync(0xffffffffu, hB, k);
            float p1 = __shfl_sync(0xffffffffu, hB, k + 1);
            unsigned long long ua0 = pk2(a0, a0), ua1 = pk2(a1, a1);
            unsigned long long up0 = pk2(p0, p0), up1 = pk2(p1, p1);
            i01a = fma2(wi0.x, ua0, i01a);
            i23a = fma2(wi0.y, ua0, i23a);
            i01b = fma2(wi1.x, ua1, i01b);
            i23b = fma2(wi1.y, ua1, i23b);
            h01a = fma2(wh0.x, up0, h01a);
            h23a = fma2(wh0.y, up0, h23a);
            h01b = fma2(wh1.x, up1, h01b);
            h23b = fma2(wh1.y, up1, h23b);
        }
        {
            float2 g01 = up2(add2(add2(i01a, i01b), add2(h01a, h01b)));
            float2 g23 = up2(add2(add2(i23a, i23b), add2(h23a, h23b)));
            float ci = sigf(g01.x), cf = sigf(g01.y);
            float cg = tanhap(g23.x), co = sigf(g23.y);
            cB = cf * cB + ci * cg;
            hB = co * tanhap(cB);
            g_h2cv[(size_t)(brow * Sdim + s) * 32 + j] = __float2half_rn(hB);
        }
    }
}

// ============================================================
// K4: mma.sync fp16 GEMM  out[18432, 14463] = h2 @ Wout^T + bias
//     [frozen R8/R12 form, measured 221.7us]
// ============================================================
#define EPI_PITCH 136
#define K4_SMEM (128 * EPI_PITCH * 4)   // 69632

__global__ __launch_bounds__(256, 2) void k_out_mma(const float* __restrict__ bout,
                                                    float* __restrict__ out) {
    extern __shared__ __align__(1024) char sm[];
    __half* As = (__half*)sm;
    __half* Bs = (__half*)(sm + 8192);
    float*  epi = (float*)sm;

    const int tid = threadIdx.x;
    const int wid = tid >> 5, lane = tid & 31;
    const int n0 = blockIdx.x * 128;
    const int m0 = blockIdx.y * 128;

    const int4* Ag = (const int4*)(g_h2cv + (size_t)m0 * 32);
    const int4* Bg = (const int4*)(g_wcv + (size_t)n0 * 32);
#pragma unroll
    for (int it = 0; it < 2; it++) {
        int idx = tid + it * 256;
        int row = idx >> 2, u = idx & 3;
        uint32_t off = (uint32_t)(row * 64 + u * 16);
        *(int4*)((char*)As + SW64(off)) = Ag[idx];
        *(int4*)((char*)Bs + SW64(off)) = Bg[idx];
    }

    float bias_r[4];
#pragma unroll
    for (int c = 0; c < 4; c++) {
        int col = n0 + c * 32 + lane;
        bias_r[c] = (col < Vdim) ? bout[col] : 0.f;
    }
    __syncthreads();

    const uint32_t As_u = smem_u32(As);
    const uint32_t Bs_u = smem_u32(Bs);

    const int mwarp = (wid & 3) * 32;
    const int nwarp = (wid >> 2) * 64;
    const int rowa = lane & 15;
    const int sega = lane >> 4;

    float acc[2][8][4];
#pragma unroll
    for (int mf = 0; mf < 2; mf++)
#pragma unroll
        for (int j = 0; j < 8; j++)
#pragma unroll
            for (int q = 0; q < 4; q++) acc[mf][j][q] = 0.f;

#pragma unroll
    for (int p = 0; p < 2; p++) {
        uint32_t a[2][4];
#pragma unroll
        for (int mf = 0; mf < 2; mf++) {
            uint32_t off = (uint32_t)((mwarp + mf * 16 + rowa) * 64 + p * 32 + sega * 16);
            LDSM_X4(a[mf][0], a[mf][1], a[mf][2], a[mf][3], As_u + SW64(off));
        }
        uint32_t bfr[8][2];
#pragma unroll
        for (int nb = 0; nb < 4; nb++) {
            uint32_t r0, r1, r2, r3;
            uint32_t off = (uint32_t)((nwarp + nb * 16 + rowa) * 64 + p * 32 + sega * 16);
            LDSM_X4(r0, r1, r2, r3, Bs_u + SW64(off));
            bfr[nb * 2][0] = r0;     bfr[nb * 2][1] = r2;
            bfr[nb * 2 + 1][0] = r1; bfr[nb * 2 + 1][1] = r3;
        }
#pragma unroll
        for (int mf = 0; mf < 2; mf++)
#pragma unroll
            for (int j = 0; j < 8; j++)
                MMA16816F16(acc[mf][j], a[mf], bfr[j]);
    }

    __syncthreads();
#pragma unroll
    for (int mf = 0; mf < 2; mf++)
#pragma unroll
        for (int j = 0; j < 8; j++) {
            int colb = nwarp + j * 8 + (lane & 3) * 2;
            int r0 = mwarp + mf * 16 + (lane >> 2);
            *(float2*)&epi[r0 * EPI_PITCH + colb] =
                make_float2(acc[mf][j][0], acc[mf][j][1]);
            *(float2*)&epi[(r0 + 8) * EPI_PITCH + colb] =
                make_float2(acc[mf][j][2], acc[mf][j][3]);
        }
    __syncthreads();

    const int rbase = wid * 16;
#pragma unroll
    for (int rr = 0; rr < 16; rr++) {
        size_t gro = (size_t)(m0 + rbase + rr) * Vdim + n0;
#pragma unroll
        for (int c = 0; c < 4; c++) {
            int col = c * 32 + lane;
            if (n0 + col < Vdim)
                out[gro + col] = epi[(rbase + rr) * EPI_PITCH + col] + bias_r[c];
        }
    }
}

// ============================================================
extern "C" void kernel_launch(void* const* d_in, const int* in_sizes, int n_in,
                              void* d_out, int out_size) {
    const float* graph = (const float*)d_in[0];
    const int*   sent  = (const int*)d_in[1];
    const float* Wg2e  = (const float*)d_in[2];
    const float* bg2e  = (const float*)d_in[3];
    const float* emb   = (const float*)d_in[4];
    const float* Wih0  = (const float*)d_in[5];
    const float* Whh0  = (const float*)d_in[6];
    const float* bih0  = (const float*)d_in[7];
    const float* bhh0  = (const float*)d_in[8];
    const float* Wih1  = (const float*)d_in[9];
    const float* Whh1  = (const float*)d_in[10];
    const float* bih1  = (const float*)d_in[11];
    const float* bhh1  = (const float*)d_in[12];
    const float* Wout  = (const float*)d_in[13];
    const float* bout  = (const float*)d_in[14];
    float* out = (float*)d_out;

    cudaFuncSetAttribute(k_out_mma, cudaFuncAttributeMaxDynamicSharedMemorySize,
                         K4_SMEM);

    k_init<<<INIT_TOTAL, 256>>>(Wout, Wg2e, Wih0, bg2e, bih0, bhh0);
    k_gxall<<<GXALL_TOTAL, 256>>>(sent, emb, Wih0, bih0, bhh0, graph);
    k_lstm<<<128, 256>>>(Whh0, Wih1, Whh1, bih1, bhh1);
    k_out_mma<<<dim3(113, 144), 256, K4_SMEM>>>(bout, out);
}